// round 2
// baseline (speedup 1.0000x reference)
#include <cuda_runtime.h>

#define Bsz 16
#define HWs 64
#define ICs 512
#define OCs 512
#define WDs 512
#define BN  64
#define CK  16

// Scratch (no allocs allowed): style vector and demod coefficient per sample.
__device__ __align__(16) float g_s[Bsz * ICs];
__device__ __align__(16) float g_d[Bsz * OCs];

// ---------------------------------------------------------------------------
// Kernel 1: style s[b,i] = (w_latents @ fc_w) * fc_coef + fc_b + 1
// ---------------------------------------------------------------------------
__global__ void style_k(const float* __restrict__ wl,
                        const float* __restrict__ fcw,
                        const float* __restrict__ fcb) {
    int b = blockIdx.x;
    int i = threadIdx.x;              // 512 threads
    __shared__ float sh[WDs];
    sh[i] = wl[b * WDs + i];
    __syncthreads();
    float acc = 0.f;
#pragma unroll 8
    for (int d = 0; d < WDs; d++)
        acc = fmaf(sh[d], fcw[d * ICs + i], acc);
    const float fc_coef = 0.04419417382415922f;   // 1/sqrt(512)
    g_s[b * ICs + i] = acc * fc_coef + fcb[i] + 1.0f;
}

// ---------------------------------------------------------------------------
// Kernel 2: demod  g_d[b,o] = cc * rsqrt(cc^2 * sum_{kk,i} w^2 * s^2 + 1e-8)
// (conv_coef cc folded into g_d so the main conv uses raw w and x*s)
// ---------------------------------------------------------------------------
__global__ void demod_k(const float* __restrict__ w) {
    int b = blockIdx.x;
    int o = threadIdx.x;              // 512 threads
    __shared__ float s2[ICs];
    float sv = g_s[b * ICs + o];
    s2[o] = sv * sv;
    __syncthreads();
    float acc = 0.f;
    for (int kk = 0; kk < 9; kk++) {
        const float* wp = w + (size_t)kk * ICs * OCs + o;
#pragma unroll 8
        for (int i = 0; i < ICs; i++) {
            float wv = wp[(size_t)i * OCs];
            acc = fmaf(wv * wv, s2[i], acc);
        }
    }
    const float cc = 0.014731391274719739f;       // 1/sqrt(4608)
    g_d[b * OCs + o] = cc * rsqrtf(fmaf(acc, cc * cc, 1e-8f));
}

// ---------------------------------------------------------------------------
// Kernel 3: main conv, implicit GEMM.
// Block tile: one image row (64 positions) x 64 out-channels.
// 256 threads, each a 4(M) x 4(N) microtile. K loop: 32 ic-chunks x 9 taps.
// xs: modulated input, 3 rows x 66 cols x CK (pad 17 for bank-conflict-free).
// ws3: weights for one ky (3 kx taps) x CK x 64oc, reloaded per ky.
// ---------------------------------------------------------------------------
__global__ __launch_bounds__(256)
void conv_k(const float* __restrict__ x,
            const float* __restrict__ w,
            const float* __restrict__ bias,
            float* __restrict__ out) {
    __shared__ __align__(16) float xs[3][66][CK + 1];   // 13.5 KB
    __shared__ __align__(16) float ws3[3][CK][BN];      // 12 KB
    __shared__ __align__(16) float sh_s[ICs];           // style row, 2 KB

    const int oc0 = blockIdx.x * BN;
    const int mt  = blockIdx.y;               // b*64 + h
    const int b   = mt >> 6;
    const int h   = mt & 63;

    const int tid = threadIdx.x;
    const int tx  = tid & 15;                 // N direction
    const int ty  = tid >> 4;                 // M direction

    float acc[4][4] = {};

    const float* xb = x + (size_t)b * HWs * HWs * ICs;

    for (int i = tid; i < ICs; i += 256) sh_s[i] = g_s[b * ICs + i];
    __syncthreads();

    for (int ic0 = 0; ic0 < ICs; ic0 += CK) {
        // ---- load modulated x tile: 3 rows x 66 cols x 16 ic ----
        for (int idx = tid; idx < 3 * 66 * CK; idx += 256) {
            int k  = idx & (CK - 1);
            int rc = idx >> 4;
            int c  = rc % 66;
            int r  = rc / 66;
            int row = h - 1 + r;
            int col = c - 1;
            float v = 0.f;
            if ((unsigned)row < HWs && (unsigned)col < HWs)
                v = xb[(row * HWs + col) * ICs + ic0 + k] * sh_s[ic0 + k];
            xs[r][c][k] = v;
        }

#pragma unroll 1
        for (int ky = 0; ky < 3; ky++) {
            // ---- load weights for this ky: 3 taps x 16 ic x 64 oc ----
            for (int idx = tid; idx < 3 * CK * BN; idx += 256) {
                int o  = idx & 63;
                int t2 = idx >> 6;
                int kc = t2 & 15;
                int kx = t2 >> 4;
                ws3[kx][kc][o] =
                    w[(size_t)(((ky * 3 + kx) * ICs) + ic0 + kc) * OCs + oc0 + o];
            }
            __syncthreads();

#pragma unroll 4
            for (int kc = 0; kc < CK; kc++) {
                float a[6];
#pragma unroll
                for (int j = 0; j < 6; j++) a[j] = xs[ky][ty * 4 + j][kc];
#pragma unroll
                for (int kx = 0; kx < 3; kx++) {
                    float4 bb = *(const float4*)&ws3[kx][kc][tx * 4];
#pragma unroll
                    for (int mi = 0; mi < 4; mi++) {
                        float av = a[mi + kx];
                        acc[mi][0] = fmaf(av, bb.x, acc[mi][0]);
                        acc[mi][1] = fmaf(av, bb.y, acc[mi][1]);
                        acc[mi][2] = fmaf(av, bb.z, acc[mi][2]);
                        acc[mi][3] = fmaf(av, bb.w, acc[mi][3]);
                    }
                }
            }
            __syncthreads();
        }
    }

    // ---- epilogue: y = acc * d[b,o] + bias[o] ----
    const int oc = oc0 + tx * 4;
    float4 d4  = *(const float4*)&g_d[b * OCs + oc];
    float4 bb4 = *(const float4*)&bias[oc];
#pragma unroll
    for (int mi = 0; mi < 4; mi++) {
        int wpos = ty * 4 + mi;
        float4 o4;
        o4.x = fmaf(acc[mi][0], d4.x, bb4.x);
        o4.y = fmaf(acc[mi][1], d4.y, bb4.y);
        o4.z = fmaf(acc[mi][2], d4.z, bb4.z);
        o4.w = fmaf(acc[mi][3], d4.w, bb4.w);
        *(float4*)&out[(((size_t)b * HWs + h) * HWs + wpos) * OCs + oc] = o4;
    }
}

// ---------------------------------------------------------------------------
extern "C" void kernel_launch(void* const* d_in, const int* in_sizes, int n_in,
                              void* d_out, int out_size) {
    const float* x    = (const float*)d_in[0];   // [16,64,64,512]
    const float* wl   = (const float*)d_in[1];   // [16,512]
    const float* w    = (const float*)d_in[2];   // [3,3,512,512]
    const float* bias = (const float*)d_in[3];   // [512]
    const float* fcw  = (const float*)d_in[4];   // [512,512]
    const float* fcb  = (const float*)d_in[5];   // [512]
    float* out = (float*)d_out;                  // [16,64,64,512]

    style_k<<<Bsz, WDs>>>(wl, fcw, fcb);
    demod_k<<<Bsz, OCs>>>(w);

    dim3 grid(OCs / BN, Bsz * HWs);              // (8, 1024)
    conv_k<<<grid, 256>>>(x, w, bias, out);
}

// round 4
// speedup vs baseline: 2.9197x; 2.9197x over previous
#include <cuda_runtime.h>
#include <cuda_bf16.h>
#include <cstdint>

#define Bsz 16
#define HWs 64
#define ICs 512
#define OCs 512
#define WDs 512

// ---------------- global scratch (no allocs allowed) ----------------
__device__ __align__(16) float g_s[Bsz * ICs];
__device__ __align__(16) float g_d[Bsz * OCs];
// padded modulated input, bf16 hi/lo: [b][66][66][512]
__device__ __align__(16) __nv_bfloat16 g_xph[(size_t)Bsz * 66 * 66 * ICs];
__device__ __align__(16) __nv_bfloat16 g_xpl[(size_t)Bsz * 66 * 66 * ICs];
// transposed weights [tap][oc][ic], bf16 hi/lo
__device__ __align__(16) __nv_bfloat16 g_whi[9 * ICs * OCs];
__device__ __align__(16) __nv_bfloat16 g_wlo[9 * ICs * OCs];

// ---------------- helpers ----------------
__device__ __forceinline__ uint32_t smem_u32(const void* p) {
    uint32_t a;
    asm("{ .reg .u64 t; cvta.to.shared.u64 t, %1; cvt.u32.u64 %0, t; }"
        : "=r"(a) : "l"(p));
    return a;
}

__device__ __forceinline__ void cpasync16(uint32_t dst, const void* src) {
    asm volatile("cp.async.cg.shared.global [%0], [%1], 16;"
                 :: "r"(dst), "l"(src));
}

__device__ __forceinline__ void ldm4(uint32_t* r, uint32_t addr) {
    asm volatile("ldmatrix.sync.aligned.m8n8.x4.shared.b16 {%0,%1,%2,%3}, [%4];"
                 : "=r"(r[0]), "=r"(r[1]), "=r"(r[2]), "=r"(r[3]) : "r"(addr));
}

__device__ __forceinline__ void mma16816(float* c, const uint32_t* a,
                                         const uint32_t* b) {
    asm volatile(
        "mma.sync.aligned.m16n8k16.row.col.f32.bf16.bf16.f32 "
        "{%0,%1,%2,%3}, {%4,%5,%6,%7}, {%8,%9}, {%0,%1,%2,%3};"
        : "+f"(c[0]), "+f"(c[1]), "+f"(c[2]), "+f"(c[3])
        : "r"(a[0]), "r"(a[1]), "r"(a[2]), "r"(a[3]), "r"(b[0]), "r"(b[1]));
}

// ---------------------------------------------------------------------------
// Kernel 1: style s[b,i] = (w_latents @ fc_w) * fc_coef + fc_b + 1
// ---------------------------------------------------------------------------
__global__ void style_k(const float* __restrict__ wl,
                        const float* __restrict__ fcw,
                        const float* __restrict__ fcb) {
    int b = blockIdx.x;
    int i = threadIdx.x;
    __shared__ float sh[WDs];
    sh[i] = wl[b * WDs + i];
    __syncthreads();
    float acc = 0.f;
#pragma unroll 8
    for (int d = 0; d < WDs; d++)
        acc = fmaf(sh[d], fcw[d * ICs + i], acc);
    const float fc_coef = 0.04419417382415922f;   // 1/sqrt(512)
    g_s[b * ICs + i] = acc * fc_coef + fcb[i] + 1.0f;
}

// ---------------------------------------------------------------------------
// Kernel 2: demod (fp32 exact); conv_coef folded into g_d
// ---------------------------------------------------------------------------
__global__ void demod_k(const float* __restrict__ w) {
    int b = blockIdx.x;
    int o = threadIdx.x;
    __shared__ float s2[ICs];
    float sv = g_s[b * ICs + o];
    s2[o] = sv * sv;
    __syncthreads();
    float acc = 0.f;
    for (int kk = 0; kk < 9; kk++) {
        const float* wp = w + (size_t)kk * ICs * OCs + o;
#pragma unroll 8
        for (int i = 0; i < ICs; i++) {
            float wv = wp[(size_t)i * OCs];
            acc = fmaf(wv * wv, s2[i], acc);
        }
    }
    const float cc = 0.014731391274719739f;       // 1/sqrt(4608)
    g_d[b * OCs + o] = cc * rsqrtf(fmaf(acc, cc * cc, 1e-8f));
}

// ---------------------------------------------------------------------------
// Kernel 3: modulate + split + zero-pad: x_pad[b][66][66][512] hi/lo
// grid (66, 66, 16), 128 threads, 4 ic each
// ---------------------------------------------------------------------------
__global__ __launch_bounds__(128)
void xpad_k(const float* __restrict__ x) {
    int pr = blockIdx.x, pc = blockIdx.y, b = blockIdx.z;
    int t = threadIdx.x;                       // ic4 = t*4
    size_t dsti = (((size_t)b * 66 + pr) * 66 + pc) * 128 + t;   // uint2 index
    uint2 hu = make_uint2(0, 0), lu = make_uint2(0, 0);
    if (pr >= 1 && pr <= 64 && pc >= 1 && pc <= 64) {
        size_t srci = (((size_t)b * 64 + pr - 1) * 64 + pc - 1) * 128 + t;
        float4 xv = ((const float4*)x)[srci];
        float4 sv = ((const float4*)g_s)[b * 128 + t];
        float v0 = xv.x * sv.x, v1 = xv.y * sv.y;
        float v2 = xv.z * sv.z, v3 = xv.w * sv.w;
        __nv_bfloat16 h0 = __float2bfloat16(v0), h1 = __float2bfloat16(v1);
        __nv_bfloat16 h2 = __float2bfloat16(v2), h3 = __float2bfloat16(v3);
        __nv_bfloat162 ha = {h0, h1}, hb = {h2, h3};
        __nv_bfloat162 la = {__float2bfloat16(v0 - __bfloat162float(h0)),
                             __float2bfloat16(v1 - __bfloat162float(h1))};
        __nv_bfloat162 lb = {__float2bfloat16(v2 - __bfloat162float(h2)),
                             __float2bfloat16(v3 - __bfloat162float(h3))};
        hu.x = *(uint32_t*)&ha; hu.y = *(uint32_t*)&hb;
        lu.x = *(uint32_t*)&la; lu.y = *(uint32_t*)&lb;
    }
    ((uint2*)g_xph)[dsti] = hu;
    ((uint2*)g_xpl)[dsti] = lu;
}

// ---------------------------------------------------------------------------
// Kernel 4: transpose weights [tap][ic][oc] -> [tap][oc][ic], split hi/lo
// ---------------------------------------------------------------------------
__global__ void wtrans_k(const float* __restrict__ w) {
    __shared__ float t[32][33];
    int tap = blockIdx.z, icb = blockIdx.y * 32, ocb = blockIdx.x * 32;
#pragma unroll
    for (int r = 0; r < 4; r++) {
        int iy = threadIdx.y + r * 8;
        t[iy][threadIdx.x] = w[((size_t)tap * 512 + icb + iy) * 512 + ocb + threadIdx.x];
    }
    __syncthreads();
#pragma unroll
    for (int r = 0; r < 4; r++) {
        int oy = threadIdx.y + r * 8;
        float v = t[threadIdx.x][oy];
        size_t o = ((size_t)tap * 512 + ocb + oy) * 512 + icb + threadIdx.x;
        __nv_bfloat16 h = __float2bfloat16(v);
        g_whi[o] = h;
        g_wlo[o] = __float2bfloat16(v - __bfloat162float(h));
    }
}

// ---------------------------------------------------------------------------
// Kernel 5: main conv. CTA: M=256 positions (4 image rows) x N=128 oc.
// 256 threads = 8 warps (2 warpM x 4 warpN), warp tile m128 x n32.
// Units: ky(3) x ic-chunk(32 of 16ic). Per unit: A window 4rows x 66cols,
// B = 3 kx taps x 128 oc. kx -> A address offset. 3-product bf16 split.
// ---------------------------------------------------------------------------
#define STRD 48
#define A_SEG 12672          // 264 slots * 48
#define A_BUF 25344
#define B_BASE 50688
#define B_SEG 18432          // 384 slots * 48
#define B_BUF 36864
#define SMEM_TOTAL 124416

__global__ __launch_bounds__(256, 1)
void conv_k(const float* __restrict__ bias, float* __restrict__ out) {
    extern __shared__ char smem[];
    const uint32_t sbase = smem_u32(smem);

    const int tid  = threadIdx.x;
    const int wid  = tid >> 5;
    const int lane = tid & 31;
    const int warpN = wid & 3;
    const int warpM = wid >> 2;
    const int n0 = warpN * 32;

    const int bid   = blockIdx.x;
    const int oc0   = (bid & 3) << 7;
    const int mtile = bid >> 2;
    const int b     = mtile >> 4;
    const int h0    = (mtile & 15) << 2;
    const int m0g   = mtile << 8;

    float acc[8][4][4] = {};

    // per-lane ldmatrix offsets
    const uint32_t aoff = (uint32_t)((lane & 15) * STRD + ((lane >> 4) << 4));
    const uint32_t boff = (uint32_t)(((lane & 7) + ((lane >> 4) << 3)) * STRD
                                     + (((lane >> 3) & 1) << 4));

    // ---- staging lambda (cp.async) ----
    auto stage = [&](int u, int buf) {
        int ky = u >> 5, chunk = u & 31;
        // A: 264 slots x 2 splits x 2 halves = 1056 16B ops
        for (int i = tid; i < 1056; i += 256) {
            int half = i & 1;
            int rest = i >> 1;
            int split = rest >= 264;
            int slot = split ? rest - 264 : rest;
            int r = slot / 66, col = slot - r * 66;
            int pr = h0 + ky + r;
            size_t gidx = (((size_t)(b * 66 + pr)) * 66 + col) * 512
                        + chunk * 16 + half * 8;
            const __nv_bfloat16* src = (split ? g_xpl : g_xph) + gidx;
            uint32_t dst = sbase + buf * A_BUF + split * A_SEG
                         + slot * STRD + half * 16;
            cpasync16(dst, src);
        }
        // B: 384 slots (3kx x 128oc) x 2 splits x 2 halves = 1536 ops
        for (int i = tid; i < 1536; i += 256) {
            int half = i & 1;
            int rest = i >> 1;
            int split = rest >= 384;
            int slot = split ? rest - 384 : rest;
            int kx = slot >> 7, ocl = slot & 127;
            size_t gidx = ((size_t)((ky * 3 + kx) * 512 + oc0 + ocl)) * 512
                        + chunk * 16 + half * 8;
            const __nv_bfloat16* src = (split ? g_wlo : g_whi) + gidx;
            uint32_t dst = sbase + B_BASE + buf * B_BUF + split * B_SEG
                         + slot * STRD + half * 16;
            cpasync16(dst, src);
        }
    };

    stage(0, 0);
    asm volatile("cp.async.commit_group;" ::: "memory");

#pragma unroll 1
    for (int u = 0; u < 96; u++) {
        const int buf = u & 1;
        if (u < 95) {
            stage(u + 1, (u + 1) & 1);
            asm volatile("cp.async.commit_group;" ::: "memory");
            asm volatile("cp.async.wait_group 1;" ::: "memory");
        } else {
            asm volatile("cp.async.wait_group 0;" ::: "memory");
        }
        __syncthreads();

        const uint32_t aH = sbase + buf * A_BUF;            // A hi
        const uint32_t aL = aH + A_SEG;                     // A lo
        const uint32_t bH = sbase + B_BASE + buf * B_BUF;   // B hi
        const uint32_t bL = bH + B_SEG;                     // B lo

#pragma unroll
        for (int kx = 0; kx < 3; kx++) {
            uint32_t Af[8][4], Bhf[2][4], Blf[2][4];
            // A slot base: ((warpM*2 + mf/4)*66 + kx + (mf%4)*16)
#pragma unroll
            for (int mf = 0; mf < 8; mf++) {
                uint32_t slotb = (uint32_t)(((warpM << 1) + (mf >> 2)) * 66
                                 + kx + ((mf & 3) << 4));
                ldm4(Af[mf], aH + slotb * STRD + aoff);
            }
#pragma unroll
            for (int p = 0; p < 2; p++) {
                uint32_t slotb = (uint32_t)((kx << 7) + n0 + (p << 4));
                ldm4(Bhf[p], bH + slotb * STRD + boff);
                ldm4(Blf[p], bL + slotb * STRD + boff);
            }
            // Ah * Bh
#pragma unroll
            for (int mf = 0; mf < 8; mf++)
#pragma unroll
                for (int nf = 0; nf < 4; nf++)
                    mma16816(acc[mf][nf], Af[mf], &Bhf[nf >> 1][(nf & 1) * 2]);
            // Ah * Bl
#pragma unroll
            for (int mf = 0; mf < 8; mf++)
#pragma unroll
                for (int nf = 0; nf < 4; nf++)
                    mma16816(acc[mf][nf], Af[mf], &Blf[nf >> 1][(nf & 1) * 2]);
            // Al * Bh (reuse Af regs)
#pragma unroll
            for (int mf = 0; mf < 8; mf++) {
                uint32_t slotb = (uint32_t)(((warpM << 1) + (mf >> 2)) * 66
                                 + kx + ((mf & 3) << 4));
                ldm4(Af[mf], aL + slotb * STRD + aoff);
            }
#pragma unroll
            for (int mf = 0; mf < 8; mf++)
#pragma unroll
                for (int nf = 0; nf < 4; nf++)
                    mma16816(acc[mf][nf], Af[mf], &Bhf[nf >> 1][(nf & 1) * 2]);
        }
        __syncthreads();
    }

    // ---- epilogue: y = acc * d + bias ----
    float* dsm = (float*)smem;
    float* bsm = (float*)smem + 128;
    if (tid < 128) {
        dsm[tid] = g_d[b * OCs + oc0 + tid];
        bsm[tid] = bias[oc0 + tid];
    }
    __syncthreads();

#pragma unroll
    for (int mf = 0; mf < 8; mf++) {
        int m = warpM * 128 + mf * 16 + (lane >> 2);
        size_t row0 = (size_t)(m0g + m) * 512 + oc0;
        size_t row1 = row0 + 8 * 512;
#pragma unroll
        for (int nf = 0; nf < 4; nf++) {
            int n = n0 + nf * 8 + (lane & 3) * 2;
            float2 v0, v1;
            v0.x = acc[mf][nf][0] * dsm[n]     + bsm[n];
            v0.y = acc[mf][nf][1] * dsm[n + 1] + bsm[n + 1];
            v1.x = acc[mf][nf][2] * dsm[n]     + bsm[n];
            v1.y = acc[mf][nf][3] * dsm[n + 1] + bsm[n + 1];
            *(float2*)&out[row0 + n] = v0;
            *(float2*)&out[row1 + n] = v1;
        }
    }
}

// ---------------------------------------------------------------------------
extern "C" void kernel_launch(void* const* d_in, const int* in_sizes, int n_in,
                              void* d_out, int out_size) {
    const float* x    = (const float*)d_in[0];   // [16,64,64,512]
    const float* wl   = (const float*)d_in[1];   // [16,512]
    const float* w    = (const float*)d_in[2];   // [3,3,512,512]
    const float* bias = (const float*)d_in[3];   // [512]
    const float* fcw  = (const float*)d_in[4];   // [512,512]
    const float* fcb  = (const float*)d_in[5];   // [512]
    float* out = (float*)d_out;                  // [16,64,64,512]

    cudaFuncSetAttribute(conv_k, cudaFuncAttributeMaxDynamicSharedMemorySize,
                         SMEM_TOTAL);

    style_k<<<Bsz, WDs>>>(wl, fcw, fcb);
    demod_k<<<Bsz, OCs>>>(w);
    xpad_k<<<dim3(66, 66, Bsz), 128>>>(x);
    wtrans_k<<<dim3(16, 16, 9), dim3(32, 8)>>>(w);
    conv_k<<<1024, 256, SMEM_TOTAL>>>(bias, out);
}

// round 5
// speedup vs baseline: 3.6152x; 1.2382x over previous
#include <cuda_runtime.h>
#include <cuda_bf16.h>
#include <cstdint>

#define Bsz 16
#define HWs 64
#define ICs 512
#define OCs 512
#define WDs 512

// ---------------- global scratch (no allocs allowed) ----------------
__device__ __align__(16) float g_s[Bsz * ICs];
__device__ __align__(16) float g_d[Bsz * OCs];
// A records: [b][chunk32][prow66] -> {hi: 66 cols x 48B, lo: 66 x 48B} = 6336B
__device__ __align__(16) char g_xA[(size_t)Bsz * 32 * 66 * 6336];
// B records: [ky3][chunk32][ocblk4][kx3] -> {hi: 128 oc x 48B, lo: 128 x 48B} = 12288B
__device__ __align__(16) char g_wB[(size_t)3 * 32 * 4 * 3 * 12288];

// ---------------- helpers ----------------
__device__ __forceinline__ uint32_t smem_u32(const void* p) {
    uint32_t a;
    asm("{ .reg .u64 t; cvta.to.shared.u64 t, %1; cvt.u32.u64 %0, t; }"
        : "=r"(a) : "l"(p));
    return a;
}

__device__ __forceinline__ void mbar_init(uint32_t a, uint32_t cnt) {
    asm volatile("mbarrier.init.shared.b64 [%0], %1;" :: "r"(a), "r"(cnt) : "memory");
}

__device__ __forceinline__ void expect_tx(uint32_t mbar, uint32_t bytes) {
    asm volatile("mbarrier.arrive.expect_tx.shared.b64 _, [%0], %1;"
                 :: "r"(mbar), "r"(bytes) : "memory");
}

__device__ __forceinline__ void bulk_ld(uint32_t dst, const void* src,
                                        uint32_t bytes, uint32_t mbar) {
    asm volatile(
        "cp.async.bulk.shared::cluster.global.mbarrier::complete_tx::bytes "
        "[%0], [%1], %2, [%3];"
        :: "r"(dst), "l"(src), "r"(bytes), "r"(mbar) : "memory");
}

__device__ __forceinline__ void waitpar(uint32_t mbar, uint32_t phase) {
    asm volatile(
        "{\n\t.reg .pred P;\n\t"
        "WL%=:\n\t"
        "mbarrier.try_wait.parity.acquire.cta.shared::cta.b64 P, [%0], %1, 0x989680;\n\t"
        "@P bra.uni WD%=;\n\t"
        "bra.uni WL%=;\n\t"
        "WD%=:\n\t}"
        :: "r"(mbar), "r"(phase) : "memory");
}

__device__ __forceinline__ void ldm4(uint32_t* r, uint32_t addr) {
    asm volatile("ldmatrix.sync.aligned.m8n8.x4.shared.b16 {%0,%1,%2,%3}, [%4];"
                 : "=r"(r[0]), "=r"(r[1]), "=r"(r[2]), "=r"(r[3]) : "r"(addr));
}

__device__ __forceinline__ void mma16816(float* c, const uint32_t* a,
                                         const uint32_t* b) {
    asm volatile(
        "mma.sync.aligned.m16n8k16.row.col.f32.bf16.bf16.f32 "
        "{%0,%1,%2,%3}, {%4,%5,%6,%7}, {%8,%9}, {%0,%1,%2,%3};"
        : "+f"(c[0]), "+f"(c[1]), "+f"(c[2]), "+f"(c[3])
        : "r"(a[0]), "r"(a[1]), "r"(a[2]), "r"(a[3]), "r"(b[0]), "r"(b[1]));
}

// ---------------------------------------------------------------------------
// Kernel 1: style s[b,i] = (w_latents @ fc_w) * fc_coef + fc_b + 1
// ---------------------------------------------------------------------------
__global__ void style_k(const float* __restrict__ wl,
                        const float* __restrict__ fcw,
                        const float* __restrict__ fcb) {
    int b = blockIdx.x;
    int i = threadIdx.x;
    __shared__ float sh[WDs];
    sh[i] = wl[b * WDs + i];
    __syncthreads();
    float acc = 0.f;
#pragma unroll 8
    for (int d = 0; d < WDs; d++)
        acc = fmaf(sh[d], fcw[d * ICs + i], acc);
    const float fc_coef = 0.04419417382415922f;   // 1/sqrt(512)
    g_s[b * ICs + i] = acc * fc_coef + fcb[i] + 1.0f;
}

// ---------------------------------------------------------------------------
// Kernel 2: demod (fp32 exact); conv_coef folded into g_d
// ---------------------------------------------------------------------------
__global__ void demod_k(const float* __restrict__ w) {
    int b = blockIdx.x;
    int o = threadIdx.x;
    __shared__ float s2[ICs];
    float sv = g_s[b * ICs + o];
    s2[o] = sv * sv;
    __syncthreads();
    float acc = 0.f;
    for (int kk = 0; kk < 9; kk++) {
        const float* wp = w + (size_t)kk * ICs * OCs + o;
#pragma unroll 8
        for (int i = 0; i < ICs; i++) {
            float wv = wp[(size_t)i * OCs];
            acc = fmaf(wv * wv, s2[i], acc);
        }
    }
    const float cc = 0.014731391274719739f;       // 1/sqrt(4608)
    g_d[b * OCs + o] = cc * rsqrtf(fmaf(acc, cc * cc, 1e-8f));
}

// ---------------------------------------------------------------------------
// Kernel 3: modulate + split + zero-pad into A records
// grid (66, 66, 16), 128 threads: thread t -> chunk=t>>2 (16ic), sub=t&3 (4ic)
// ---------------------------------------------------------------------------
__global__ __launch_bounds__(128)
void xpad_k(const float* __restrict__ x) {
    int pr = blockIdx.x, pc = blockIdx.y, b = blockIdx.z;
    int t = threadIdx.x;
    int chunk = t >> 2, sub = t & 3;
    size_t base = (((size_t)(b * 32 + chunk)) * 66 + pr) * 6336 + pc * 48 + sub * 8;
    uint2 hu = make_uint2(0, 0), lu = make_uint2(0, 0);
    if (pr >= 1 && pr <= 64 && pc >= 1 && pc <= 64) {
        size_t srci = (((size_t)b * 64 + pr - 1) * 64 + pc - 1) * 128 + chunk * 4 + sub;
        float4 xv = ((const float4*)x)[srci];
        float4 sv = ((const float4*)g_s)[b * 128 + chunk * 4 + sub];
        float v0 = xv.x * sv.x, v1 = xv.y * sv.y;
        float v2 = xv.z * sv.z, v3 = xv.w * sv.w;
        __nv_bfloat16 h0 = __float2bfloat16(v0), h1 = __float2bfloat16(v1);
        __nv_bfloat16 h2 = __float2bfloat16(v2), h3 = __float2bfloat16(v3);
        __nv_bfloat162 ha = {h0, h1}, hb = {h2, h3};
        __nv_bfloat162 la = {__float2bfloat16(v0 - __bfloat162float(h0)),
                             __float2bfloat16(v1 - __bfloat162float(h1))};
        __nv_bfloat162 lb = {__float2bfloat16(v2 - __bfloat162float(h2)),
                             __float2bfloat16(v3 - __bfloat162float(h3))};
        hu.x = *(uint32_t*)&ha; hu.y = *(uint32_t*)&hb;
        lu.x = *(uint32_t*)&la; lu.y = *(uint32_t*)&lb;
    }
    *(uint2*)(g_xA + base)        = hu;
    *(uint2*)(g_xA + base + 3168) = lu;
}

// ---------------------------------------------------------------------------
// Kernel 4: weights -> B records. grid (32 chunk, 4 ocblk, 9 tap), 128 thr (oc r)
// ---------------------------------------------------------------------------
__global__ __launch_bounds__(128)
void wtrans_k(const float* __restrict__ w) {
    int chunk = blockIdx.x, ocblk = blockIdx.y, tap = blockIdx.z;
    int ky = tap / 3, kx = tap - ky * 3;
    int r = threadIdx.x;
    int oc = ocblk * 128 + r;
    __nv_bfloat16 hi[16], lo[16];
#pragma unroll
    for (int i = 0; i < 16; i++) {
        float v = w[((size_t)tap * 512 + chunk * 16 + i) * 512 + oc];
        __nv_bfloat16 h = __float2bfloat16(v);
        hi[i] = h;
        lo[i] = __float2bfloat16(v - __bfloat162float(h));
    }
    size_t base = ((((size_t)ky * 32 + chunk) * 4 + ocblk) * 3 + kx) * 12288 + r * 48;
    *(uint4*)(g_wB + base)          = *(uint4*)&hi[0];
    *(uint4*)(g_wB + base + 16)     = *(uint4*)&hi[8];
    *(uint4*)(g_wB + base + 6144)      = *(uint4*)&lo[0];
    *(uint4*)(g_wB + base + 6144 + 16) = *(uint4*)&lo[8];
}

// ---------------------------------------------------------------------------
// Kernel 5: main conv. CTA: M=256 positions (4 rows) x N=128 oc, 256 threads.
// 96 units (chunk-major, ky inner). A staged once per chunk (6 rows, all ky),
// B once per unit (3 kx). Both via single cp.async.bulk ops, double-buffered.
// ---------------------------------------------------------------------------
#define MB_B0 0
#define MB_B1 8
#define MB_A0 16
#define MB_A1 24
#define A_BUF0 64
#define A_BYTES 38016
#define A_BUF1 (A_BUF0 + A_BYTES)
#define B_BUF0 (A_BUF1 + A_BYTES)
#define B_BYTES 36864
#define B_BUF1 (B_BUF0 + B_BYTES)
#define SMEM_TOTAL (B_BUF1 + B_BYTES)   // 149,824 B

__global__ __launch_bounds__(256, 1)
void conv_k(const float* __restrict__ bias, float* __restrict__ out) {
    extern __shared__ char smem[];
    const uint32_t sb = smem_u32(smem);

    const int tid  = threadIdx.x;
    const int wid  = tid >> 5;
    const int lane = tid & 31;
    const int warpN = wid & 3;
    const int warpM = wid >> 2;
    const int n0 = warpN * 32;

    const int bid   = blockIdx.x;
    const int ocblk = bid & 3;
    const int oc0   = ocblk << 7;
    const int mtile = bid >> 2;
    const int b     = mtile >> 4;
    const int h0    = (mtile & 15) << 2;
    const int m0g   = mtile << 8;

    float acc[8][4][4] = {};

    const uint32_t aoff = (uint32_t)((lane & 15) * 48 + ((lane >> 4) << 4));
    const uint32_t boff = (uint32_t)(((lane & 7) + ((lane >> 4) << 3)) * 48
                                     + (((lane >> 3) & 1) << 4));

    if (tid == 0) {
        mbar_init(sb + MB_B0, 1); mbar_init(sb + MB_B1, 1);
        mbar_init(sb + MB_A0, 1); mbar_init(sb + MB_A1, 1);
    }
    __syncthreads();

    // producer: issue bulk loads for A chunk / B unit
    auto issueA = [&](int chunk, int buf) {
        const char* src = g_xA + (((size_t)(b * 32 + chunk)) * 66 + h0) * 6336;
        uint32_t mb = sb + MB_A0 + buf * 8;
        expect_tx(mb, A_BYTES);
        bulk_ld(sb + A_BUF0 + buf * A_BYTES, src, A_BYTES, mb);
    };
    auto issueB = [&](int u, int buf) {
        int chunk = u / 3, ky = u - 3 * chunk;
        const char* src = g_wB + ((((size_t)ky * 32 + chunk) * 4 + ocblk) * 3) * 12288;
        uint32_t mb = sb + MB_B0 + buf * 8;
        expect_tx(mb, B_BYTES);
        bulk_ld(sb + B_BUF0 + buf * B_BYTES, src, B_BYTES, mb);
    };

    if (tid == 0) { issueA(0, 0); issueB(0, 0); }

#pragma unroll 1
    for (int u = 0; u < 96; u++) {
        const int chunk = u / 3;
        const int ky    = u - 3 * chunk;

        // prefetch next (buffers last read two iterations ago -> safe)
        if (tid == 0) {
            int nx = u + 1;
            if (nx < 96) {
                issueB(nx, nx & 1);
                if (nx - 3 * (nx / 3) == 0) issueA(nx / 3, (nx / 3) & 1);
            }
        }

        waitpar(sb + MB_B0 + (u & 1) * 8, (u >> 1) & 1);
        if (ky == 0)
            waitpar(sb + MB_A0 + (chunk & 1) * 8, (chunk >> 1) & 1);

        const uint32_t aB = sb + A_BUF0 + (chunk & 1) * A_BYTES;
        const uint32_t bB = sb + B_BUF0 + (u & 1) * B_BYTES;

#pragma unroll
        for (int kx = 0; kx < 3; kx++) {
            uint32_t Af[8][4], Bhf[2][4], Blf[2][4];
#pragma unroll
            for (int mf = 0; mf < 8; mf++) {
                uint32_t base = aB + (uint32_t)(((warpM << 1) + (mf >> 2)) + ky) * 6336
                              + (uint32_t)(kx + ((mf & 3) << 4)) * 48 + aoff;
                ldm4(Af[mf], base);
            }
#pragma unroll
            for (int p = 0; p < 2; p++) {
                uint32_t base = bB + kx * 12288 + (uint32_t)(n0 + (p << 4)) * 48 + boff;
                ldm4(Bhf[p], base);
                ldm4(Blf[p], base + 6144);
            }
            // Ah*Bh
#pragma unroll
            for (int mf = 0; mf < 8; mf++)
#pragma unroll
                for (int nf = 0; nf < 4; nf++)
                    mma16816(acc[mf][nf], Af[mf], &Bhf[nf >> 1][(nf & 1) * 2]);
            // Ah*Bl
#pragma unroll
            for (int mf = 0; mf < 8; mf++)
#pragma unroll
                for (int nf = 0; nf < 4; nf++)
                    mma16816(acc[mf][nf], Af[mf], &Blf[nf >> 1][(nf & 1) * 2]);
            // Al*Bh
#pragma unroll
            for (int mf = 0; mf < 8; mf++) {
                uint32_t base = aB + (uint32_t)(((warpM << 1) + (mf >> 2)) + ky) * 6336
                              + 3168 + (uint32_t)(kx + ((mf & 3) << 4)) * 48 + aoff;
                ldm4(Af[mf], base);
            }
#pragma unroll
            for (int mf = 0; mf < 8; mf++)
#pragma unroll
                for (int nf = 0; nf < 4; nf++)
                    mma16816(acc[mf][nf], Af[mf], &Bhf[nf >> 1][(nf & 1) * 2]);
        }
        __syncthreads();
    }

    // ---- epilogue: y = acc * d + bias ----
    float* dsm = (float*)(smem + 64);
    float* bsm = (float*)(smem + 64 + 512);
    if (tid < 128) {
        dsm[tid] = g_d[b * OCs + oc0 + tid];
        bsm[tid] = bias[oc0 + tid];
    }
    __syncthreads();

#pragma unroll
    for (int mf = 0; mf < 8; mf++) {
        int m = warpM * 128 + mf * 16 + (lane >> 2);
        size_t row0 = (size_t)(m0g + m) * 512 + oc0;
        size_t row1 = row0 + 8 * 512;
#pragma unroll
        for (int nf = 0; nf < 4; nf++) {
            int n = n0 + nf * 8 + (lane & 3) * 2;
            float2 v0, v1;
            v0.x = acc[mf][nf][0] * dsm[n]     + bsm[n];
            v0.y = acc[mf][nf][1] * dsm[n + 1] + bsm[n + 1];
            v1.x = acc[mf][nf][2] * dsm[n]     + bsm[n];
            v1.y = acc[mf][nf][3] * dsm[n + 1] + bsm[n + 1];
            *(float2*)&out[row0 + n] = v0;
            *(float2*)&out[row1 + n] = v1;
        }
    }
}

// ---------------------------------------------------------------------------
extern "C" void kernel_launch(void* const* d_in, const int* in_sizes, int n_in,
                              void* d_out, int out_size) {
    const float* x    = (const float*)d_in[0];   // [16,64,64,512]
    const float* wl   = (const float*)d_in[1];   // [16,512]
    const float* w    = (const float*)d_in[2];   // [3,3,512,512]
    const float* bias = (const float*)d_in[3];   // [512]
    const float* fcw  = (const float*)d_in[4];   // [512,512]
    const float* fcb  = (const float*)d_in[5];   // [512]
    float* out = (float*)d_out;                  // [16,64,64,512]

    cudaFuncSetAttribute(conv_k, cudaFuncAttributeMaxDynamicSharedMemorySize,
                         SMEM_TOTAL);

    style_k<<<Bsz, WDs>>>(wl, fcw, fcb);
    demod_k<<<Bsz, OCs>>>(w);
    xpad_k<<<dim3(66, 66, Bsz), 128>>>(x);
    wtrans_k<<<dim3(32, 4, 9), 128>>>(w);
    conv_k<<<1024, 256, SMEM_TOTAL>>>(bias, out);
}